// round 12
// baseline (speedup 1.0000x reference)
#include <cuda_runtime.h>
#include <math.h>

#define Bb   512
#define Dd   64
#define Tt   256
#define RNN  100
#define G3   300
#define RPB  4
#define NTHR 928

typedef unsigned long long u64;

__device__ float g_states[Tt*Bb*65];
__device__ float g_gib[Tt*Bb*G3];
__device__ float g_gif[Tt*Bb*G3];
__device__ float g_dict[257*128*400];     // interleaved [key][blk][k*4+r]
__device__ int   g_obs[Tt];
__device__ float g_Fft[4*G3*52];          // fused fwd-gi, thread-major [lvl][j][52]
__device__ float g_Fbt[4*G3*52];          // fused bwd-gi, thread-major
__device__ float g_bff[4*G3];
__device__ float g_bfb[4*G3];
__device__ float g_decWt[4*50*208];       // decoder, thread-major [lvl][jo][seg*52+kk]
__device__ float g_meanWt[4*64*52];       // mean, thread-major [lvl][dcol][k]

__device__ __forceinline__ float tanh_ap(float x){ float r; asm("tanh.approx.f32 %0, %1;":"=f"(r):"f"(x)); return r; }
__device__ __forceinline__ float sigm2(float x){ return 0.5f + 0.5f*tanh_ap(0.5f*x); }
__device__ __forceinline__ u64 ffma2(u64 a,u64 b,u64 c){ u64 d; asm("fma.rn.f32x2 %0, %1, %2, %3;":"=l"(d):"l"(a),"l"(b),"l"(c)); return d; }
__device__ __forceinline__ u64 dup2(float x){ u64 d; asm("mov.b64 %0, {%1, %1};":"=l"(d):"f"(x)); return d; }

__device__ __forceinline__ void st_ghp(float* ghp,int kh,int j,u64 a01,u64 a23){
    float f0,f1,f2,f3;
    asm("mov.b64 {%0,%1},%2;":"=f"(f0),"=f"(f1):"l"(a01));
    asm("mov.b64 {%0,%1},%2;":"=f"(f2),"=f"(f3):"l"(a23));
    float* p=ghp+kh*1200+j;
    p[0]=f0; p[300]=f1; p[600]=f2; p[900]=f3;
}

__device__ __forceinline__ void mv_reg(const float (&u)[34], const float* h4f, float* ghp,
                                       int tid,int j,int kh,int k0,int kc){
    if (tid<900){
        u64 a01=0ull, a23=0ull;
        const ulonglong2* h2=(const ulonglong2*)h4f;
        #pragma unroll
        for (int i=0;i<34;i++) if (i<kc){
            u64 w=dup2(u[i]);
            ulonglong2 x=h2[k0+i];
            a01=ffma2(x.x,w,a01); a23=ffma2(x.y,w,a23);
        }
        st_ghp(ghp,kh,j,a01,a23);
    }
}
__device__ __forceinline__ void mv_smem(const float* __restrict__ U, const float* h4f, float* ghp,
                                        int tid,int j,int kh,int k0,int kc){
    if (tid<900){
        u64 a01=0ull, a23=0ull;
        const ulonglong2* h2=(const ulonglong2*)h4f;
        #pragma unroll
        for (int i=0;i<34;i++) if (i<kc){
            u64 w=dup2(U[(k0+i)*G3+j]);
            ulonglong2 x=h2[k0+i];
            a01=ffma2(x.x,w,a01); a23=ffma2(x.y,w,a23);
        }
        st_ghp(ghp,kh,j,a01,a23);
    }
}

__device__ __forceinline__ void gates4(const float* ghp, const float* gi, int giStride,
                                       const float* b1s, float* h4f, float* dictDst, int tid){
    if (tid<400){
        int jj=tid>>2, r=tid&3;
        int o=r*300+jj;
        float ghz=ghp[o]    +ghp[1200+o]    +ghp[2400+o]    +b1s[jj];
        float ghr=ghp[o+100]+ghp[1200+o+100]+ghp[2400+o+100]+b1s[jj+100];
        float ghn=ghp[o+200]+ghp[1200+o+200]+ghp[2400+o+200]+b1s[jj+200];
        const float* g=gi+r*giStride;
        float z =sigm2(g[jj]     + ghz);
        float rr=sigm2(g[jj+100] + ghr);
        float n =tanh_ap(g[jj+200] + rr*ghn);
        float hn=z*h4f[tid]+(1.f-z)*n;
        h4f[tid]=hn;
        if (dictDst) dictDst[tid]=hn;
    }
}

__global__ void k_sched(const float* __restrict__ a){
    int t=threadIdx.x;
    if (t<Tt) g_obs[t] = (a[t*3+2] > 0.5f) ? 1 : 0;
}

// tiled transpose: a[B,D,T,3] -> g_states[t][b][65]
__global__ void k_states(const float* __restrict__ a){
    __shared__ float tile[64][66];
    int b=blockIdx.x, t0=blockIdx.y*64;
    int tid=threadIdx.x;
    for (int i=tid;i<4096;i+=256){
        int c=i>>6, tt=i&63;
        tile[tt][c]=a[((b*Dd+c)*Tt+t0+tt)*3];
    }
    if (tid<64) tile[tid][64]=a[((b*Dd)*Tt+t0+tid)*3+2];
    __syncthreads();
    for (int i=tid;i<4160;i+=256){
        int tt=i/65, c=i-tt*65;
        g_states[((t0+tt)*Bb+b)*65+c]=tile[tt][c];
    }
}

// fused fill matrices, thread-major + padded (pads zeroed)
__global__ void k_fuse(const float* __restrict__ gruW, const float* __restrict__ gruB,
                       const float* __restrict__ bgruW, const float* __restrict__ bgruB,
                       const float* __restrict__ meanW, const float* __restrict__ meanB){
    int lvl=blockIdx.x, j=threadIdx.x;
    if (j>=G3) return;
    int kk=blockIdx.y;
    const float* mW=meanW+lvl*3200;
    const float* mb=meanB+lvl*64;
    if (kk<50){
        float sf=0.f, sb=0.f;
        for (int m=0;m<64;m++){
            float w=mW[kk*64+m];
            if (m>=1) sf=fmaf(w, gruW[(m-1)*G3+j], sf);
            sb=fmaf(w, bgruW[m*G3+j], sb);
        }
        g_Fft[(lvl*G3+j)*52+kk]=sf;
        g_Fbt[(lvl*G3+j)*52+kk]=sb;
    } else {
        float bf=gruB[j]+gruW[63*G3+j];
        float bb=bgruB[j]+bgruW[64*G3+j];
        for (int m=0;m<64;m++){
            if (m>=1) bf=fmaf(mb[m], gruW[(m-1)*G3+j], bf);
            bb=fmaf(mb[m], bgruW[m*G3+j], bb);
        }
        g_bff[lvl*G3+j]=bf;
        g_bfb[lvl*G3+j]=bb;
        g_Fft[(lvl*G3+j)*52+50]=0.f; g_Fft[(lvl*G3+j)*52+51]=0.f;
        g_Fbt[(lvl*G3+j)*52+50]=0.f; g_Fbt[(lvl*G3+j)*52+51]=0.f;
    }
}

// transpose decW/meanW to thread-major padded layouts
__global__ void k_trn(const float* __restrict__ decW, const float* __restrict__ meanW){
    int idx=blockIdx.x*blockDim.x+threadIdx.x;
    if (idx < 4*50*208){
        int col=idx%208, row=idx/208;
        int jo=row%50, lvl=row/50;
        int seg=col/52, kk=col-seg*52;
        g_decWt[idx] = (kk<50)? decW[lvl*10000+(seg*50+kk)*50+jo] : 0.f;
    } else if (idx < 4*50*208 + 4*64*52){
        int i2=idx-4*50*208;
        int k=i2%52, row=i2/52;
        int d=row%64, lvl=row/64;
        g_meanWt[i2] = (k<50)? meanW[lvl*3200+k*64+d] : 0.f;
    }
}

// gi precompute, float4-vectorized x reads (stride 68 = 17 float4 per row).
__global__ void __launch_bounds__(320) k_gi(const float* __restrict__ gruW, const float* __restrict__ gruB,
                                            const float* __restrict__ bgruW, const float* __restrict__ bgruB){
    __shared__ __align__(16) float xs[16*68];
    int t=blockIdx.x>>5;
    int b0=(blockIdx.x&31)*16;
    int mode=blockIdx.y;
    if (mode==0 && t==0) return;
    if (mode==1 && t>0 && !g_obs[t]) return;
    int tid=threadIdx.x;
    for (int i=tid;i<16*65;i+=320){
        int r=i/65,c=i-r*65;
        float v=g_states[(t*Bb+b0+r)*65+c];
        if (mode==0)          xs[r*68+c]=v;
        else if (c>=1)        xs[r*68+c-1]=v;
    }
    __syncthreads();
    if (tid>=G3) return;
    const float* W = mode? gruW : bgruW;
    float bias     = mode? gruB[tid] : bgruB[tid];
    float acc[16];
    #pragma unroll
    for (int r=0;r<16;r++) acc[r]=bias;
    const float4* xs4=(const float4*)xs;
    #pragma unroll 4
    for (int c4=0;c4<16;c4++){
        float w0=W[(4*c4+0)*G3+tid];
        float w1=W[(4*c4+1)*G3+tid];
        float w2=W[(4*c4+2)*G3+tid];
        float w3=W[(4*c4+3)*G3+tid];
        #pragma unroll
        for (int r=0;r<16;r++){
            float4 v=xs4[r*17+c4];
            acc[r]=fmaf(v.x,w0,acc[r]);
            acc[r]=fmaf(v.y,w1,acc[r]);
            acc[r]=fmaf(v.z,w2,acc[r]);
            acc[r]=fmaf(v.w,w3,acc[r]);
        }
    }
    if (mode==0){
        float w=W[64*G3+tid];
        #pragma unroll
        for (int r=0;r<16;r++) acc[r]=fmaf(xs[r*68+64],w,acc[r]);
    }
    float* out = mode? g_gif : g_gib;
    #pragma unroll
    for (int r=0;r<16;r++) out[(t*Bb+b0+r)*G3+tid]=acc[r];
}

__global__ void __launch_bounds__(NTHR,1) k_back(const float* __restrict__ bgruU, const float* __restrict__ bgruB){
    __shared__ float ghp[3600];
    __shared__ float gi_s[1200];
    __shared__ __align__(16) float h4f[400];
    __shared__ float sbb1[300];
    int tid=threadIdx.x, blk=blockIdx.x, b0=blk*RPB;
    int kh=tid/300, j=tid-kh*300;
    int k0c=(kh==0)?0:((kh==1)?34:67);
    int kcC=(kh==0)?34:33;
    float uB[34];
    if (tid<900){
        #pragma unroll
        for (int i=0;i<34;i++) if (i<kcC) uB[i]=bgruU[(k0c+i)*G3+j];
    }
    if (tid<G3) sbb1[tid]=bgruB[G3+tid];
    if (tid<400){ h4f[tid]=0.f; g_dict[(256*128+blk)*400+tid]=0.f; }
    __syncthreads();
    for (int t=Tt-1;t>=1;t--){
        const float* src=g_gib+(t*Bb+b0)*G3;
        float f0=src[tid];
        float f1=(tid<272)? src[tid+NTHR] : 0.f;
        mv_reg(uB,h4f,ghp,tid,j,kh,k0c,kcC);
        gi_s[tid]=f0;
        if (tid<272) gi_s[tid+NTHR]=f1;
        __syncthreads();
        gates4(ghp,gi_s,G3,sbb1,h4f,(t>=2)? g_dict+(t*128+blk)*400 : (float*)0, tid);
        __syncthreads();
    }
}

// dyn smem (words): sUg 0..30000 | ghp 30000..33600 | gi_s 33600..34800 | h4f 34800..35200
// | hb4f 35200..35600 | dec4 35600..35800 | decp 35800..36600 | sb0 36600..36900
// | sbb1 36900..37200 | sgb1 37200..37500   total 37500 words = 150000 B
__global__ void __launch_bounds__(NTHR,1) k_fwd(
        const float* __restrict__ gruU, const float* __restrict__ gruB,
        const float* __restrict__ bgruU, const float* __restrict__ bgruB,
        const float* __restrict__ decB, const float* __restrict__ meanB){
    extern __shared__ float sm[];
    float* sUg =sm;
    float* ghp =sm+30000;
    float* gi_s=sm+33600;
    float* h4f =sm+34800;
    float* hb4f=sm+35200;
    float* dec4=sm+35600;
    float* decp=sm+35800;
    float* sb0 =sm+36600;
    float* sbb1=sm+36900;
    float* sgb1=sm+37200;
    __shared__ int obs_s[Tt];

    int tid=threadIdx.x, blk=blockIdx.x, b0=blk*RPB;
    int kh=tid/300, j=tid-kh*300;
    int k0c=(kh==0)?0:((kh==1)?34:67);
    int kcC=(kh==0)?34:33;
    float uB[34];
    if (tid<900){
        #pragma unroll
        for (int i=0;i<34;i++) if (i<kcC) uB[i]=bgruU[(k0c+i)*G3+j];
    }
    for (int i=tid;i<RNN*G3;i+=NTHR) sUg[i]=gruU[i];
    if (tid<G3){ sb0[tid]=bgruB[tid]; sbb1[tid]=bgruB[G3+tid]; sgb1[tid]=gruB[G3+tid]; }
    if (tid<400) h4f[tid]=0.f;
    if (tid<Tt) obs_s[tid]=g_obs[tid];
    __syncthreads();

    bool skip=false;
    // initial forward cell: t=0
    {
        const float* src=g_gif+(0*Bb+b0)*G3;
        float f0=src[tid];
        float f1=(tid<272)? src[tid+NTHR] : 0.f;
        mv_smem(sUg,h4f,ghp,tid,j,kh,k0c,kcC);
        gi_s[tid]=f0;
        if (tid<272) gi_s[tid+NTHR]=f1;
        __syncthreads();
        gates4(ghp,gi_s,G3,sgb1,h4f,(float*)0,tid);
        __syncthreads();
    }

    int curr_p=0;
    while (curr_p < Tt-1){
        if (obs_s[curr_p+1]){
            curr_p++;
            float f0=0.f,f1=0.f;
            if (!skip){
                const float* src=g_gif+(curr_p*Bb+b0)*G3;
                f0=src[tid];
                if (tid<272) f1=src[tid+NTHR];
            }
            mv_smem(sUg,h4f,ghp,tid,j,kh,k0c,kcC);
            if (!skip){
                gi_s[tid]=f0;
                if (tid<272) gi_s[tid+NTHR]=f1;
            }
            skip=false;
            __syncthreads();
            gates4(ghp,gi_s,G3,sgb1,h4f,(float*)0,tid);
            __syncthreads();
        } else {
            int next_p=curr_p+1;
            while (next_p<Tt && !obs_s[next_p]) next_p++;
            int step=1;
            while (curr_p+2*step<=next_p && step<=8) step<<=1;
            if (step>1) step>>=1;
            int lvl=(step==8)?3:((step==4)?2:((step==2)?1:0));
            int tf=curr_p+step;
            int fl=(step>1);

            // P2': decoder partials; seg 2,3 read hb straight from g_dict (L2)
            if (tid<800){
                int seg=tid/200, o=tid-seg*200;
                int r=o/50, jo=o-r*50;
                const float4* wt=(const float4*)(g_decWt+(lvl*50+jo)*208+seg*52);
                float acc=0.f;
                if (seg<2){
                    const float* hsrc=h4f+seg*200;
                    #pragma unroll
                    for (int q=0;q<13;q++){
                        float4 w=wt[q];
                        acc=fmaf(hsrc[(4*q+0)*4+r],w.x,acc);
                        acc=fmaf(hsrc[(4*q+1)*4+r],w.y,acc);
                        acc=fmaf(hsrc[(4*q+2)*4+r],w.z,acc);
                        acc=fmaf(hsrc[(4*q+3)*4+r],w.w,acc);
                    }
                } else {
                    const float* dsrc=g_dict+((curr_p+2*step)*128+blk)*400+(seg-2)*200;
                    #pragma unroll
                    for (int q=0;q<13;q++){
                        float4 w=wt[q];
                        acc=fmaf(dsrc[(4*q+0)*4+r],w.x,acc);
                        acc=fmaf(dsrc[(4*q+1)*4+r],w.y,acc);
                        acc=fmaf(dsrc[(4*q+2)*4+r],w.z,acc);
                        acc=fmaf(dsrc[(4*q+3)*4+r],w.w,acc);
                    }
                }
                decp[seg*200+o]=acc;
            }
            __syncthreads();

            // P3: reduce + relu -> dec4 interleaved [k*4+r]
            if (tid<200){
                int r=tid/50, jo=tid-r*50;
                int o=r*50+jo;
                float v=decp[o]+decp[200+o]+decp[400+o]+decp[600+o]+decB[lvl*50+jo];
                dec4[jo*4+r]=fmaxf(v,0.f);
            }
            __syncthreads();

            // P4: merged — fwd-gi || bwd-gi(if fl) || mean || hb(right+1) prefetch
            if (tid<300){
                u64 a01=dup2(g_bff[lvl*G3+tid]), a23=a01;
                const ulonglong2* dp=(const ulonglong2*)dec4;
                const float4* Fp=(const float4*)(g_Fft+(lvl*G3+tid)*52);
                #pragma unroll
                for (int q=0;q<13;q++){
                    float4 w=Fp[q];
                    ulonglong2 x0=dp[4*q],x1=dp[4*q+1],x2=dp[4*q+2],x3=dp[4*q+3];
                    u64 w0=dup2(w.x),w1=dup2(w.y),w2=dup2(w.z),w3=dup2(w.w);
                    a01=ffma2(x0.x,w0,a01); a23=ffma2(x0.y,w0,a23);
                    a01=ffma2(x1.x,w1,a01); a23=ffma2(x1.y,w1,a23);
                    a01=ffma2(x2.x,w2,a01); a23=ffma2(x2.y,w2,a23);
                    a01=ffma2(x3.x,w3,a01); a23=ffma2(x3.y,w3,a23);
                }
                float f0,f1,f2,f3;
                asm("mov.b64 {%0,%1},%2;":"=f"(f0),"=f"(f1):"l"(a01));
                asm("mov.b64 {%0,%1},%2;":"=f"(f2),"=f"(f3):"l"(a23));
                float* dst=g_gif+(tf*Bb+b0)*G3+tid;
                dst[0]=f0; dst[300]=f1; dst[600]=f2; dst[900]=f3;
                if (!fl){
                    gi_s[tid]=f0; gi_s[300+tid]=f1; gi_s[600+tid]=f2; gi_s[900+tid]=f3;
                }
            } else if (tid<600){
                if (fl){
                    int jq=tid-300;
                    u64 a01=dup2(g_bfb[lvl*G3+jq]), a23=a01;
                    const ulonglong2* dp=(const ulonglong2*)dec4;
                    const float4* Fp=(const float4*)(g_Fbt+(lvl*G3+jq)*52);
                    #pragma unroll
                    for (int q=0;q<13;q++){
                        float4 w=Fp[q];
                        ulonglong2 x0=dp[4*q],x1=dp[4*q+1],x2=dp[4*q+2],x3=dp[4*q+3];
                        u64 w0=dup2(w.x),w1=dup2(w.y),w2=dup2(w.z),w3=dup2(w.w);
                        a01=ffma2(x0.x,w0,a01); a23=ffma2(x0.y,w0,a23);
                        a01=ffma2(x1.x,w1,a01); a23=ffma2(x1.y,w1,a23);
                        a01=ffma2(x2.x,w2,a01); a23=ffma2(x2.y,w2,a23);
                        a01=ffma2(x3.x,w3,a01); a23=ffma2(x3.y,w3,a23);
                    }
                    float f0,f1,f2,f3;
                    asm("mov.b64 {%0,%1},%2;":"=f"(f0),"=f"(f1):"l"(a01));
                    asm("mov.b64 {%0,%1},%2;":"=f"(f2),"=f"(f3):"l"(a23));
                    gi_s[jq]=f0; gi_s[300+jq]=f1; gi_s[600+jq]=f2; gi_s[900+jq]=f3;
                }
            } else if (tid<856){
                int idx=tid-600;
                int r=idx>>6, dcol=idx&63;
                const float4* mwt=(const float4*)(g_meanWt+(lvl*64+dcol)*52);
                float acc=meanB[lvl*64+dcol];
                #pragma unroll
                for (int q=0;q<13;q++){
                    float4 w=mwt[q];
                    acc=fmaf(dec4[(4*q+0)*4+r],w.x,acc);
                    acc=fmaf(dec4[(4*q+1)*4+r],w.y,acc);
                    acc=fmaf(dec4[(4*q+2)*4+r],w.z,acc);
                    acc=fmaf(dec4[(4*q+3)*4+r],w.w,acc);
                }
                g_states[(tf*Bb+b0+r)*65+dcol]=acc;
            } else {
                if (tid<860) g_states[(tf*Bb+b0+(tid-856))*65+64]=1.f;
                if (fl){
                    int e=tid-856;
                    float v[6];
                    #pragma unroll
                    for (int q=0;q<6;q++){ int i2=e+q*72; v[q]=(i2<400)? g_dict[((tf+1)*128+blk)*400+i2] : 0.f; }
                    #pragma unroll
                    for (int q=0;q<6;q++){ int i2=e+q*72; if (i2<400) hb4f[i2]=v[q]; }
                }
            }
            __syncthreads();

            if (fl){
                int right=tf, left=curr_p+step/2;
                mv_reg(uB,hb4f,ghp,tid,j,kh,k0c,kcC);
                __syncthreads();
                gates4(ghp,gi_s,G3,sbb1,hb4f,g_dict+(right*128+blk)*400,tid);
                __syncthreads();
                for (int ii=right-1; ii>=left; ii--){
                    mv_reg(uB,hb4f,ghp,tid,j,kh,k0c,kcC);
                    __syncthreads();
                    gates4(ghp,sb0,0,sbb1,hb4f,g_dict+(ii*128+blk)*400,tid);
                    __syncthreads();
                }
            } else {
                skip=true;
            }
            obs_s[tf]=1;
        }
    }
}

// tiled transpose: g_states[t][b][1+c] -> out[b][c][t]
__global__ void k_out(float* __restrict__ out){
    __shared__ float tile[64][65];
    int b=blockIdx.x, t0=blockIdx.y*64;
    int tid=threadIdx.x;
    for (int i=tid;i<4096;i+=256){
        int tt=i>>6, c=i&63;
        tile[tt][c]=g_states[((t0+tt)*Bb+b)*65+1+c];
    }
    __syncthreads();
    for (int i=tid;i<4096;i+=256){
        int c=i>>6, tt=i&63;
        out[(b*Dd+c)*Tt+t0+tt]=tile[tt][c];
    }
}

extern "C" void kernel_launch(void* const* d_in, const int* in_sizes, int n_in,
                              void* d_out, int out_size){
    const float* a    =(const float*)d_in[0];
    const float* gruW =(const float*)d_in[1];
    const float* gruU =(const float*)d_in[2];
    const float* gruB =(const float*)d_in[3];
    const float* bgruW=(const float*)d_in[4];
    const float* bgruU=(const float*)d_in[5];
    const float* bgruB=(const float*)d_in[6];
    const float* decW =(const float*)d_in[7];
    const float* decB =(const float*)d_in[8];
    const float* meanW=(const float*)d_in[9];
    const float* meanB=(const float*)d_in[10];
    float* out=(float*)d_out;

    cudaFuncSetAttribute(k_fwd, cudaFuncAttributeMaxDynamicSharedMemorySize, 37500*4);

    k_sched<<<1,256>>>(a);
    k_states<<<dim3(Bb,4),256>>>(a);
    k_fuse<<<dim3(4,51),G3>>>(gruW,gruB,bgruW,bgruB,meanW,meanB);
    k_trn<<<(4*50*208+4*64*52+255)/256,256>>>(decW,meanW);
    dim3 g2(Tt*32,2);
    k_gi<<<g2,320>>>(gruW,gruB,bgruW,bgruB);
    k_back<<<Bb/RPB,NTHR>>>(bgruU,bgruB);
    k_fwd<<<Bb/RPB,NTHR,37500*4>>>(gruU,gruB,bgruU,bgruB,decB,meanB);
    k_out<<<dim3(Bb,4),256>>>(out);
}

// round 14
// speedup vs baseline: 2.2196x; 2.2196x over previous
#include <cuda_runtime.h>
#include <math.h>

#define Bb   512
#define Dd   64
#define Tt   256
#define RNN  100
#define G3   300
#define RPB  4
#define NTHR 928

typedef unsigned long long u64;

__device__ float g_states[Tt*Bb*65];
__device__ float g_gib[Tt*Bb*G3];
__device__ float g_gif[Tt*Bb*G3];
__device__ float g_dict[257*128*400];   // interleaved [key][blk][k*4+r]
__device__ int   g_obs[Tt];
__device__ float g_Ff[4*50*G3];         // fused fwd-gi  [lvl][k][j]
__device__ float g_Fb[4*50*G3];         // fused bwd-gi  [lvl][k][j]
__device__ float g_bff[4*G3];
__device__ float g_bfb[4*G3];

__device__ __forceinline__ float tanh_ap(float x){ float r; asm("tanh.approx.f32 %0, %1;":"=f"(r):"f"(x)); return r; }
__device__ __forceinline__ float sigm2(float x){ return 0.5f + 0.5f*tanh_ap(0.5f*x); }
__device__ __forceinline__ u64 ffma2(u64 a,u64 b,u64 c){ u64 d; asm("fma.rn.f32x2 %0, %1, %2, %3;":"=l"(d):"l"(a),"l"(b),"l"(c)); return d; }
__device__ __forceinline__ u64 dup2(float x){ u64 d; asm("mov.b64 %0, {%1, %1};":"=l"(d):"f"(x)); return d; }

__device__ __forceinline__ void st_ghp(float* ghp,int kh,int j,u64 a01,u64 a23){
    float f0,f1,f2,f3;
    asm("mov.b64 {%0,%1},%2;":"=f"(f0),"=f"(f1):"l"(a01));
    asm("mov.b64 {%0,%1},%2;":"=f"(f2),"=f"(f3):"l"(a23));
    float* p=ghp+kh*1200+j;
    p[0]=f0; p[300]=f1; p[600]=f2; p[900]=f3;
}

__device__ __forceinline__ void mv_reg(const float (&u)[34], const float* h4f, float* ghp,
                                       int tid,int j,int kh,int k0,int kc){
    if (tid<900){
        u64 a01=0ull, a23=0ull;
        const ulonglong2* h2=(const ulonglong2*)h4f;
        #pragma unroll
        for (int i=0;i<34;i++) if (i<kc){
            u64 w=dup2(u[i]);
            ulonglong2 x=h2[k0+i];
            a01=ffma2(x.x,w,a01); a23=ffma2(x.y,w,a23);
        }
        st_ghp(ghp,kh,j,a01,a23);
    }
}
__device__ __forceinline__ void mv_smem(const float* __restrict__ U, const float* h4f, float* ghp,
                                        int tid,int j,int kh,int k0,int kc){
    if (tid<900){
        u64 a01=0ull, a23=0ull;
        const ulonglong2* h2=(const ulonglong2*)h4f;
        #pragma unroll
        for (int i=0;i<34;i++) if (i<kc){
            u64 w=dup2(U[(k0+i)*G3+j]);
            ulonglong2 x=h2[k0+i];
            a01=ffma2(x.x,w,a01); a23=ffma2(x.y,w,a23);
        }
        st_ghp(ghp,kh,j,a01,a23);
    }
}

__device__ __forceinline__ void gates4(const float* ghp, const float* gi, int giStride,
                                       const float* b1s, float* h4f, float* dictDst, int tid){
    if (tid<400){
        int jj=tid>>2, r=tid&3;
        int o=r*300+jj;
        float ghz=ghp[o]    +ghp[1200+o]    +ghp[2400+o]    +b1s[jj];
        float ghr=ghp[o+100]+ghp[1200+o+100]+ghp[2400+o+100]+b1s[jj+100];
        float ghn=ghp[o+200]+ghp[1200+o+200]+ghp[2400+o+200]+b1s[jj+200];
        const float* g=gi+r*giStride;
        float z =sigm2(g[jj]     + ghz);
        float rr=sigm2(g[jj+100] + ghr);
        float n =tanh_ap(g[jj+200] + rr*ghn);
        float hn=z*h4f[tid]+(1.f-z)*n;
        h4f[tid]=hn;
        if (dictDst) dictDst[tid]=hn;
    }
}

__global__ void k_sched(const float* __restrict__ a){
    int t=threadIdx.x;
    if (t<Tt) g_obs[t] = (a[t*3+2] > 0.5f) ? 1 : 0;
}

// tiled transpose: a[B,D,T,3] -> g_states[t][b][65]
__global__ void k_states(const float* __restrict__ a){
    __shared__ float tile[64][66];
    int b=blockIdx.x, t0=blockIdx.y*64;
    int tid=threadIdx.x;
    for (int i=tid;i<4096;i+=256){
        int c=i>>6, tt=i&63;
        tile[tt][c]=a[((b*Dd+c)*Tt+t0+tt)*3];
    }
    if (tid<64) tile[tid][64]=a[((b*Dd)*Tt+t0+tid)*3+2];
    __syncthreads();
    for (int i=tid;i<4160;i+=256){
        int tt=i/65, c=i-tt*65;
        g_states[((t0+tt)*Bb+b)*65+c]=tile[tt][c];
    }
}

// fused fill matrices (R7/R9 derivation, column-major [lvl][k][j])
__global__ void k_fuse(const float* __restrict__ gruW, const float* __restrict__ gruB,
                       const float* __restrict__ bgruW, const float* __restrict__ bgruB,
                       const float* __restrict__ meanW, const float* __restrict__ meanB){
    int lvl=blockIdx.x, j=threadIdx.x;
    if (j>=G3) return;
    int kk=blockIdx.y;
    const float* mW=meanW+lvl*3200;
    const float* mb=meanB+lvl*64;
    if (kk<50){
        float sf=0.f, sb=0.f;
        for (int m=0;m<64;m++){
            float w=mW[kk*64+m];
            if (m>=1) sf=fmaf(w, gruW[(m-1)*G3+j], sf);
            sb=fmaf(w, bgruW[m*G3+j], sb);
        }
        g_Ff[(lvl*50+kk)*G3+j]=sf;
        g_Fb[(lvl*50+kk)*G3+j]=sb;
    } else {
        float bf=gruB[j]+gruW[63*G3+j];
        float bb=bgruB[j]+bgruW[64*G3+j];
        for (int m=0;m<64;m++){
            if (m>=1) bf=fmaf(mb[m], gruW[(m-1)*G3+j], bf);
            bb=fmaf(mb[m], bgruW[m*G3+j], bb);
        }
        g_bff[lvl*G3+j]=bf;
        g_bfb[lvl*G3+j]=bb;
    }
}

// gi precompute, float4-vectorized x reads (stride 68 = 17 float4 per row).
__global__ void __launch_bounds__(320) k_gi(const float* __restrict__ gruW, const float* __restrict__ gruB,
                                            const float* __restrict__ bgruW, const float* __restrict__ bgruB){
    __shared__ __align__(16) float xs[16*68];
    int t=blockIdx.x>>5;
    int b0=(blockIdx.x&31)*16;
    int mode=blockIdx.y;
    if (mode==0 && t==0) return;
    if (mode==1 && t>0 && !g_obs[t]) return;
    int tid=threadIdx.x;
    for (int i=tid;i<16*65;i+=320){
        int r=i/65,c=i-r*65;
        float v=g_states[(t*Bb+b0+r)*65+c];
        if (mode==0)          xs[r*68+c]=v;
        else if (c>=1)        xs[r*68+c-1]=v;
    }
    __syncthreads();
    if (tid>=G3) return;
    const float* W = mode? gruW : bgruW;
    float bias     = mode? gruB[tid] : bgruB[tid];
    float acc[16];
    #pragma unroll
    for (int r=0;r<16;r++) acc[r]=bias;
    const float4* xs4=(const float4*)xs;
    #pragma unroll 4
    for (int c4=0;c4<16;c4++){
        float w0=W[(4*c4+0)*G3+tid];
        float w1=W[(4*c4+1)*G3+tid];
        float w2=W[(4*c4+2)*G3+tid];
        float w3=W[(4*c4+3)*G3+tid];
        #pragma unroll
        for (int r=0;r<16;r++){
            float4 v=xs4[r*17+c4];
            acc[r]=fmaf(v.x,w0,acc[r]);
            acc[r]=fmaf(v.y,w1,acc[r]);
            acc[r]=fmaf(v.z,w2,acc[r]);
            acc[r]=fmaf(v.w,w3,acc[r]);
        }
    }
    if (mode==0){
        float w=W[64*G3+tid];
        #pragma unroll
        for (int r=0;r<16;r++) acc[r]=fmaf(xs[r*68+64],w,acc[r]);
    }
    float* out = mode? g_gif : g_gib;
    #pragma unroll
    for (int r=0;r<16;r++) out[(t*Bb+b0+r)*G3+tid]=acc[r];
}

__global__ void __launch_bounds__(NTHR,1) k_back(const float* __restrict__ bgruU, const float* __restrict__ bgruB){
    __shared__ float ghp[3600];
    __shared__ float gi_s[1200];
    __shared__ __align__(16) float h4f[400];
    __shared__ float sbb1[300];
    int tid=threadIdx.x, blk=blockIdx.x, b0=blk*RPB;
    int kh=tid/300, j=tid-kh*300;
    int k0c=(kh==0)?0:((kh==1)?34:67);
    int kcC=(kh==0)?34:33;
    float uB[34];
    if (tid<900){
        #pragma unroll
        for (int i=0;i<34;i++) if (i<kcC) uB[i]=bgruU[(k0c+i)*G3+j];
    }
    if (tid<G3) sbb1[tid]=bgruB[G3+tid];
    if (tid<400){ h4f[tid]=0.f; g_dict[(256*128+blk)*400+tid]=0.f; }
    __syncthreads();
    for (int t=Tt-1;t>=1;t--){
        const float* src=g_gib+(t*Bb+b0)*G3;
        float f0=src[tid];
        float f1=(tid<272)? src[tid+NTHR] : 0.f;
        mv_reg(uB,h4f,ghp,tid,j,kh,k0c,kcC);
        gi_s[tid]=f0;
        if (tid<272) gi_s[tid+NTHR]=f1;
        __syncthreads();
        gates4(ghp,gi_s,G3,sbb1,h4f,(t>=2)? g_dict+(t*128+blk)*400 : (float*)0, tid);
        __syncthreads();
    }
}

// dyn smem (words): sUg 0..30000 | ghp 30000..33600 | gi_s 33600..34800 | h4f 34800..35200
// | hb4f 35200..35600 | dec4 35600..35800 | decp 35800..36600 | sb0 36600..36900
// | sbb1 36900..37200 | sgb1 37200..37500   total 37500 words = 150000 B
__global__ void __launch_bounds__(NTHR,1) k_fwd(
        const float* __restrict__ gruU, const float* __restrict__ gruB,
        const float* __restrict__ bgruU, const float* __restrict__ bgruB,
        const float* __restrict__ decW, const float* __restrict__ decB,
        const float* __restrict__ meanW, const float* __restrict__ meanB){
    extern __shared__ float sm[];
    float* sUg =sm;
    float* ghp =sm+30000;
    float* gi_s=sm+33600;
    float* h4f =sm+34800;
    float* hb4f=sm+35200;
    float* dec4=sm+35600;
    float* decp=sm+35800;
    float* sb0 =sm+36600;
    float* sbb1=sm+36900;
    float* sgb1=sm+37200;
    __shared__ int obs_s[Tt];

    int tid=threadIdx.x, blk=blockIdx.x, b0=blk*RPB;
    int kh=tid/300, j=tid-kh*300;
    int k0c=(kh==0)?0:((kh==1)?34:67);
    int kcC=(kh==0)?34:33;
    float uB[34];
    if (tid<900){
        #pragma unroll
        for (int i=0;i<34;i++) if (i<kcC) uB[i]=bgruU[(k0c+i)*G3+j];
    }
    for (int i=tid;i<RNN*G3;i+=NTHR) sUg[i]=gruU[i];
    if (tid<G3){ sb0[tid]=bgruB[tid]; sbb1[tid]=bgruB[G3+tid]; sgb1[tid]=gruB[G3+tid]; }
    if (tid<400) h4f[tid]=0.f;
    if (tid<Tt) obs_s[tid]=g_obs[tid];
    __syncthreads();

    bool skip=false;
    // initial forward cell: t=0
    {
        const float* src=g_gif+(0*Bb+b0)*G3;
        float f0=src[tid];
        float f1=(tid<272)? src[tid+NTHR] : 0.f;
        mv_smem(sUg,h4f,ghp,tid,j,kh,k0c,kcC);
        gi_s[tid]=f0;
        if (tid<272) gi_s[tid+NTHR]=f1;
        __syncthreads();
        gates4(ghp,gi_s,G3,sgb1,h4f,(float*)0,tid);
        __syncthreads();
    }

    int curr_p=0;
    while (curr_p < Tt-1){
        if (obs_s[curr_p+1]){
            curr_p++;
            float f0=0.f,f1=0.f;
            if (!skip){
                const float* src=g_gif+(curr_p*Bb+b0)*G3;
                f0=src[tid];
                if (tid<272) f1=src[tid+NTHR];
            }
            mv_smem(sUg,h4f,ghp,tid,j,kh,k0c,kcC);
            if (!skip){
                gi_s[tid]=f0;
                if (tid<272) gi_s[tid+NTHR]=f1;
            }
            skip=false;
            __syncthreads();
            gates4(ghp,gi_s,G3,sgb1,h4f,(float*)0,tid);
            __syncthreads();
        } else {
            int next_p=curr_p+1;
            while (next_p<Tt && !obs_s[next_p]) next_p++;
            int step=1;
            while (curr_p+2*step<=next_p && step<=8) step<<=1;
            if (step>1) step>>=1;
            int lvl=(step==8)?3:((step==4)?2:((step==2)?1:0));
            int tf=curr_p+step;
            int fl=(step>1);

            // P1: hb = dict[curr+2*step]
            if (tid<400) hb4f[tid]=g_dict[((curr_p+2*step)*128+blk)*400+tid];
            __syncthreads();

            // P2: decoder partials over cat[h,hb] (full unroll -> MLP 50)
            if (tid<800){
                int seg=tid/200, o=tid-seg*200;
                int r=o/50, jo=o-r*50;
                const float* dW=decW+lvl*10000+(seg*50)*50+jo;
                const float* hsrc=(seg<2)? (h4f+(seg&1)*200) : (hb4f+(seg&1)*200);
                float acc=0.f;
                #pragma unroll
                for (int kk=0;kk<50;kk++)
                    acc=fmaf(hsrc[kk*4+r], dW[kk*50], acc);
                decp[seg*200+o]=acc;
            }
            __syncthreads();

            // P3: reduce + relu -> dec4 interleaved [k*4+r]
            if (tid<200){
                int r=tid/50, jo=tid-r*50;
                int o=r*50+jo;
                float v=decp[o]+decp[200+o]+decp[400+o]+decp[600+o]+decB[lvl*50+jo];
                dec4[jo*4+r]=fmaxf(v,0.f);
            }
            __syncthreads();

            // P4: merged — fwd-gi || bwd-gi(if fl) || mean || hb(right+1) prefetch
            if (tid<300){
                u64 a01=dup2(g_bff[lvl*G3+tid]), a23=a01;
                const ulonglong2* dp=(const ulonglong2*)dec4;
                const float* Fp=g_Ff + (lvl*50)*G3 + tid;
                #pragma unroll
                for (int k=0;k<50;k++){
                    u64 w=dup2(Fp[k*G3]);
                    ulonglong2 x=dp[k];
                    a01=ffma2(x.x,w,a01); a23=ffma2(x.y,w,a23);
                }
                float f0,f1,f2,f3;
                asm("mov.b64 {%0,%1},%2;":"=f"(f0),"=f"(f1):"l"(a01));
                asm("mov.b64 {%0,%1},%2;":"=f"(f2),"=f"(f3):"l"(a23));
                float* dst=g_gif+(tf*Bb+b0)*G3+tid;
                dst[0]=f0; dst[300]=f1; dst[600]=f2; dst[900]=f3;
                if (!fl){
                    gi_s[tid]=f0; gi_s[300+tid]=f1; gi_s[600+tid]=f2; gi_s[900+tid]=f3;
                }
            } else if (tid<600){
                if (fl){
                    int jq=tid-300;
                    u64 a01=dup2(g_bfb[lvl*G3+jq]), a23=a01;
                    const ulonglong2* dp=(const ulonglong2*)dec4;
                    const float* Fp=g_Fb + (lvl*50)*G3 + jq;
                    #pragma unroll
                    for (int k=0;k<50;k++){
                        u64 w=dup2(Fp[k*G3]);
                        ulonglong2 x=dp[k];
                        a01=ffma2(x.x,w,a01); a23=ffma2(x.y,w,a23);
                    }
                    float f0,f1,f2,f3;
                    asm("mov.b64 {%0,%1},%2;":"=f"(f0),"=f"(f1):"l"(a01));
                    asm("mov.b64 {%0,%1},%2;":"=f"(f2),"=f"(f3):"l"(a23));
                    gi_s[jq]=f0; gi_s[300+jq]=f1; gi_s[600+jq]=f2; gi_s[900+jq]=f3;
                }
            } else if (tid<856){
                int idx=tid-600;
                int r=idx>>6, dcol=idx&63;
                const float* mW=meanW+lvl*3200;
                float acc=meanB[lvl*64+dcol];
                #pragma unroll
                for (int k=0;k<50;k++) acc=fmaf(dec4[k*4+r], mW[k*64+dcol], acc);
                g_states[(tf*Bb+b0+r)*65+dcol]=acc;
            } else {
                if (tid<860) g_states[(tf*Bb+b0+(tid-856))*65+64]=1.f;
                if (fl){
                    int e=tid-856;
                    float v[6];
                    #pragma unroll
                    for (int q=0;q<6;q++){ int i2=e+q*72; v[q]=(i2<400)? g_dict[((tf+1)*128+blk)*400+i2] : 0.f; }
                    #pragma unroll
                    for (int q=0;q<6;q++){ int i2=e+q*72; if (i2<400) hb4f[i2]=v[q]; }
                }
            }
            __syncthreads();

            if (fl){
                int right=tf, left=curr_p+step/2;
                mv_reg(uB,hb4f,ghp,tid,j,kh,k0c,kcC);
                __syncthreads();
                gates4(ghp,gi_s,G3,sbb1,hb4f,g_dict+(right*128+blk)*400,tid);
                __syncthreads();
                for (int ii=right-1; ii>=left; ii--){
                    mv_reg(uB,hb4f,ghp,tid,j,kh,k0c,kcC);
                    __syncthreads();
                    gates4(ghp,sb0,0,sbb1,hb4f,g_dict+(ii*128+blk)*400,tid);
                    __syncthreads();
                }
            } else {
                skip=true;
            }
            obs_s[tf]=1;
        }
    }
}

// tiled transpose: g_states[t][b][1+c] -> out[b][c][t]
__global__ void k_out(float* __restrict__ out){
    __shared__ float tile[64][65];
    int b=blockIdx.x, t0=blockIdx.y*64;
    int tid=threadIdx.x;
    for (int i=tid;i<4096;i+=256){
        int tt=i>>6, c=i&63;
        tile[tt][c]=g_states[((t0+tt)*Bb+b)*65+1+c];
    }
    __syncthreads();
    for (int i=tid;i<4096;i+=256){
        int c=i>>6, tt=i&63;
        out[(b*Dd+c)*Tt+t0+tt]=tile[tt][c];
    }
}

extern "C" void kernel_launch(void* const* d_in, const int* in_sizes, int n_in,
                              void* d_out, int out_size){
    const float* a    =(const float*)d_in[0];
    const float* gruW =(const float*)d_in[1];
    const float* gruU =(const float*)d_in[2];
    const float* gruB =(const float*)d_in[3];
    const float* bgruW=(const float*)d_in[4];
    const float* bgruU=(const float*)d_in[5];
    const float* bgruB=(const float*)d_in[6];
    const float* decW =(const float*)d_in[7];
    const float* decB =(const float*)d_in[8];
    const float* meanW=(const float*)d_in[9];
    const float* meanB=(const float*)d_in[10];
    float* out=(float*)d_out;

    cudaFuncSetAttribute(k_fwd, cudaFuncAttributeMaxDynamicSharedMemorySize, 37500*4);

    k_sched<<<1,256>>>(a);
    k_states<<<dim3(Bb,4),256>>>(a);
    k_fuse<<<dim3(4,51),G3>>>(gruW,gruB,bgruW,bgruB,meanW,meanB);
    dim3 g2(Tt*32,2);
    k_gi<<<g2,320>>>(gruW,gruB,bgruW,bgruB);
    k_back<<<Bb/RPB,NTHR>>>(bgruU,bgruB);
    k_fwd<<<Bb/RPB,NTHR,37500*4>>>(gruU,gruB,bgruU,bgruB,decW,decB,meanW,meanB);
    k_out<<<dim3(Bb,4),256>>>(out);
}

// round 16
// speedup vs baseline: 2.2295x; 1.0045x over previous
#include <cuda_runtime.h>
#include <math.h>

#define Bb   512
#define Dd   64
#define Tt   256
#define RNN  100
#define G3   300
#define RPB  4
#define NTHR 928

typedef unsigned long long u64;

__device__ float g_states[Tt*Bb*65];
__device__ float g_gib[Tt*Bb*G3];
__device__ float g_gif[Tt*Bb*G3];
__device__ float g_dict[257*128*400];   // interleaved [key][blk][k*4+r]
__device__ int   g_obs[Tt];
__device__ float g_Ff[4*50*G3];         // fused fwd-gi  [lvl][k][j]
__device__ float g_Fb[4*50*G3];         // fused bwd-gi  [lvl][k][j]
__device__ float g_bff[4*G3];
__device__ float g_bfb[4*G3];

__device__ __forceinline__ float tanh_ap(float x){ float r; asm("tanh.approx.f32 %0, %1;":"=f"(r):"f"(x)); return r; }
__device__ __forceinline__ float sigm2(float x){ return 0.5f + 0.5f*tanh_ap(0.5f*x); }
__device__ __forceinline__ u64 ffma2(u64 a,u64 b,u64 c){ u64 d; asm("fma.rn.f32x2 %0, %1, %2, %3;":"=l"(d):"l"(a),"l"(b),"l"(c)); return d; }
__device__ __forceinline__ u64 dup2(float x){ u64 d; asm("mov.b64 %0, {%1, %1};":"=l"(d):"f"(x)); return d; }

__device__ __forceinline__ void st_ghp(float* ghp,int kh,int j,u64 a01,u64 a23){
    float f0,f1,f2,f3;
    asm("mov.b64 {%0,%1},%2;":"=f"(f0),"=f"(f1):"l"(a01));
    asm("mov.b64 {%0,%1},%2;":"=f"(f2),"=f"(f3):"l"(a23));
    float* p=ghp+kh*1200+j;
    p[0]=f0; p[300]=f1; p[600]=f2; p[900]=f3;
}

__device__ __forceinline__ void mv_reg(const float (&u)[34], const float* h4f, float* ghp,
                                       int tid,int j,int kh,int k0,int kc){
    if (tid<900){
        u64 a01=0ull, a23=0ull;
        const ulonglong2* h2=(const ulonglong2*)h4f;
        #pragma unroll
        for (int i=0;i<34;i++) if (i<kc){
            u64 w=dup2(u[i]);
            ulonglong2 x=h2[k0+i];
            a01=ffma2(x.x,w,a01); a23=ffma2(x.y,w,a23);
        }
        st_ghp(ghp,kh,j,a01,a23);
    }
}
__device__ __forceinline__ void mv_smem(const float* __restrict__ U, const float* h4f, float* ghp,
                                        int tid,int j,int kh,int k0,int kc){
    if (tid<900){
        u64 a01=0ull, a23=0ull;
        const ulonglong2* h2=(const ulonglong2*)h4f;
        #pragma unroll
        for (int i=0;i<34;i++) if (i<kc){
            u64 w=dup2(U[(k0+i)*G3+j]);
            ulonglong2 x=h2[k0+i];
            a01=ffma2(x.x,w,a01); a23=ffma2(x.y,w,a23);
        }
        st_ghp(ghp,kh,j,a01,a23);
    }
}

__device__ __forceinline__ void gates4(const float* ghp, const float* gi, int giStride,
                                       const float* b1s, float* h4f, float* dictDst, int tid){
    if (tid<400){
        int jj=tid>>2, r=tid&3;
        int o=r*300+jj;
        float ghz=ghp[o]    +ghp[1200+o]    +ghp[2400+o]    +b1s[jj];
        float ghr=ghp[o+100]+ghp[1200+o+100]+ghp[2400+o+100]+b1s[jj+100];
        float ghn=ghp[o+200]+ghp[1200+o+200]+ghp[2400+o+200]+b1s[jj+200];
        const float* g=gi+r*giStride;
        float z =sigm2(g[jj]     + ghz);
        float rr=sigm2(g[jj+100] + ghr);
        float n =tanh_ap(g[jj+200] + rr*ghn);
        float hn=z*h4f[tid]+(1.f-z)*n;
        h4f[tid]=hn;
        if (dictDst) dictDst[tid]=hn;
    }
}

// tiled transpose: a[B,D,T,3] -> g_states[t][b][65]; block(0,0) also builds g_obs
__global__ void k_states(const float* __restrict__ a){
    __shared__ float tile[64][66];
    int b=blockIdx.x, t0=blockIdx.y*64;
    int tid=threadIdx.x;
    if (b==0 && blockIdx.y==0 && tid<Tt)
        g_obs[tid] = (a[tid*3+2] > 0.5f) ? 1 : 0;
    for (int i=tid;i<4096;i+=256){
        int c=i>>6, tt=i&63;
        tile[tt][c]=a[((b*Dd+c)*Tt+t0+tt)*3];
    }
    if (tid<64) tile[tid][64]=a[((b*Dd)*Tt+t0+tid)*3+2];
    __syncthreads();
    for (int i=tid;i<4160;i+=256){
        int tt=i/65, c=i-tt*65;
        g_states[((t0+tt)*Bb+b)*65+c]=tile[tt][c];
    }
}

// gi precompute (modes 0/1) + fused fill matrices (mode 2).
// xs interleaved [k][16] so packed f32x2 row-pairs load as ulonglong2.
__global__ void __launch_bounds__(320) k_gi(const float* __restrict__ gruW, const float* __restrict__ gruB,
                                            const float* __restrict__ bgruW, const float* __restrict__ bgruB,
                                            const float* __restrict__ meanW, const float* __restrict__ meanB){
    int mode=blockIdx.y;
    int tid=threadIdx.x;
    if (mode==2){   // fused fill matrices (was k_fuse)
        int bx=blockIdx.x;
        if (bx>=204 || tid>=G3) return;
        int lvl=bx/51, kk=bx%51, j=tid;
        const float* mW=meanW+lvl*3200;
        const float* mb=meanB+lvl*64;
        if (kk<50){
            float sf=0.f, sb=0.f;
            for (int m=0;m<64;m++){
                float w=mW[kk*64+m];
                if (m>=1) sf=fmaf(w, gruW[(m-1)*G3+j], sf);
                sb=fmaf(w, bgruW[m*G3+j], sb);
            }
            g_Ff[(lvl*50+kk)*G3+j]=sf;
            g_Fb[(lvl*50+kk)*G3+j]=sb;
        } else {
            float bf=gruB[j]+gruW[63*G3+j];
            float bb=bgruB[j]+bgruW[64*G3+j];
            for (int m=0;m<64;m++){
                if (m>=1) bf=fmaf(mb[m], gruW[(m-1)*G3+j], bf);
                bb=fmaf(mb[m], bgruW[m*G3+j], bb);
            }
            g_bff[lvl*G3+j]=bf;
            g_bfb[lvl*G3+j]=bb;
        }
        return;
    }
    __shared__ __align__(16) float xs[1056];   // [k][16], k<66
    int t=blockIdx.x>>5;
    int b0=(blockIdx.x&31)*16;
    if (mode==0 && t==0) return;
    if (mode==1 && t>0 && !g_obs[t]) return;
    for (int i=tid;i<16*65;i+=320){
        int r=i/65, c=i-r*65;
        float v=g_states[(t*Bb+b0+r)*65+c];
        if (mode==0)       xs[c*16+r]=v;
        else if (c>=1)     xs[(c-1)*16+r]=v;
    }
    __syncthreads();
    if (tid>=G3) return;
    const float* W = mode? gruW : bgruW;
    float bias     = mode? gruB[tid] : bgruB[tid];
    u64 acc[8];
    {
        u64 bi=dup2(bias);
        #pragma unroll
        for (int p=0;p<8;p++) acc[p]=bi;
    }
    const ulonglong2* xs2=(const ulonglong2*)xs;
    #pragma unroll 4
    for (int k=0;k<64;k++){
        u64 w=dup2(W[k*G3+tid]);
        ulonglong2 x0=xs2[k*4], x1=xs2[k*4+1], x2=xs2[k*4+2], x3=xs2[k*4+3];
        acc[0]=ffma2(x0.x,w,acc[0]); acc[1]=ffma2(x0.y,w,acc[1]);
        acc[2]=ffma2(x1.x,w,acc[2]); acc[3]=ffma2(x1.y,w,acc[3]);
        acc[4]=ffma2(x2.x,w,acc[4]); acc[5]=ffma2(x2.y,w,acc[5]);
        acc[6]=ffma2(x3.x,w,acc[6]); acc[7]=ffma2(x3.y,w,acc[7]);
    }
    if (mode==0){
        u64 w=dup2(W[64*G3+tid]);
        ulonglong2 x0=xs2[256], x1=xs2[257], x2=xs2[258], x3=xs2[259];
        acc[0]=ffma2(x0.x,w,acc[0]); acc[1]=ffma2(x0.y,w,acc[1]);
        acc[2]=ffma2(x1.x,w,acc[2]); acc[3]=ffma2(x1.y,w,acc[3]);
        acc[4]=ffma2(x2.x,w,acc[4]); acc[5]=ffma2(x2.y,w,acc[5]);
        acc[6]=ffma2(x3.x,w,acc[6]); acc[7]=ffma2(x3.y,w,acc[7]);
    }
    float* out = (mode? g_gif : g_gib) + (t*Bb+b0)*G3 + tid;
    #pragma unroll
    for (int p=0;p<8;p++){
        float lo,hi;
        asm("mov.b64 {%0,%1},%2;":"=f"(lo),"=f"(hi):"l"(acc[p]));
        out[(2*p)*G3]=lo; out[(2*p+1)*G3]=hi;
    }
}

__global__ void __launch_bounds__(NTHR,1) k_back(const float* __restrict__ bgruU, const float* __restrict__ bgruB){
    __shared__ float ghp[3600];
    __shared__ float gi_s[1200];
    __shared__ __align__(16) float h4f[400];
    __shared__ float sbb1[300];
    int tid=threadIdx.x, blk=blockIdx.x, b0=blk*RPB;
    int kh=tid/300, j=tid-kh*300;
    int k0c=(kh==0)?0:((kh==1)?34:67);
    int kcC=(kh==0)?34:33;
    float uB[34];
    if (tid<900){
        #pragma unroll
        for (int i=0;i<34;i++) if (i<kcC) uB[i]=bgruU[(k0c+i)*G3+j];
    }
    if (tid<G3) sbb1[tid]=bgruB[G3+tid];
    if (tid<400){ h4f[tid]=0.f; g_dict[(256*128+blk)*400+tid]=0.f; }
    __syncthreads();
    for (int t=Tt-1;t>=1;t--){
        const float* src=g_gib+(t*Bb+b0)*G3;
        float f0=src[tid];
        float f1=(tid<272)? src[tid+NTHR] : 0.f;
        mv_reg(uB,h4f,ghp,tid,j,kh,k0c,kcC);
        gi_s[tid]=f0;
        if (tid<272) gi_s[tid+NTHR]=f1;
        __syncthreads();
        gates4(ghp,gi_s,G3,sbb1,h4f,(t>=2)? g_dict+(t*128+blk)*400 : (float*)0, tid);
        __syncthreads();
    }
}

// dyn smem (words): sUg 0..30000 | ghp 30000..33600 | gi_s 33600..34800 | h4f 34800..35200
// | hb4f 35200..35600 | dec4 35600..35800 | decp 35800..36600 | sb0 36600..36900
// | sbb1 36900..37200 | sgb1 37200..37500   total 37500 words = 150000 B
__global__ void __launch_bounds__(NTHR,1) k_fwd(
        const float* __restrict__ gruU, const float* __restrict__ gruB,
        const float* __restrict__ bgruU, const float* __restrict__ bgruB,
        const float* __restrict__ decW, const float* __restrict__ decB,
        const float* __restrict__ meanW, const float* __restrict__ meanB){
    extern __shared__ float sm[];
    float* sUg =sm;
    float* ghp =sm+30000;
    float* gi_s=sm+33600;
    float* h4f =sm+34800;
    float* hb4f=sm+35200;
    float* dec4=sm+35600;
    float* decp=sm+35800;
    float* sb0 =sm+36600;
    float* sbb1=sm+36900;
    float* sgb1=sm+37200;
    __shared__ int obs_s[Tt];

    int tid=threadIdx.x, blk=blockIdx.x, b0=blk*RPB;
    int kh=tid/300, j=tid-kh*300;
    int k0c=(kh==0)?0:((kh==1)?34:67);
    int kcC=(kh==0)?34:33;
    float uB[34];
    if (tid<900){
        #pragma unroll
        for (int i=0;i<34;i++) if (i<kcC) uB[i]=bgruU[(k0c+i)*G3+j];
    }
    for (int i=tid;i<RNN*G3;i+=NTHR) sUg[i]=gruU[i];
    if (tid<G3){ sb0[tid]=bgruB[tid]; sbb1[tid]=bgruB[G3+tid]; sgb1[tid]=gruB[G3+tid]; }
    if (tid<400) h4f[tid]=0.f;
    if (tid<Tt) obs_s[tid]=g_obs[tid];
    __syncthreads();

    bool skip=false;
    // initial forward cell: t=0
    {
        const float* src=g_gif+(0*Bb+b0)*G3;
        float f0=src[tid];
        float f1=(tid<272)? src[tid+NTHR] : 0.f;
        mv_smem(sUg,h4f,ghp,tid,j,kh,k0c,kcC);
        gi_s[tid]=f0;
        if (tid<272) gi_s[tid+NTHR]=f1;
        __syncthreads();
        gates4(ghp,gi_s,G3,sgb1,h4f,(float*)0,tid);
        __syncthreads();
    }

    int curr_p=0;
    while (curr_p < Tt-1){
        if (obs_s[curr_p+1]){
            curr_p++;
            float f0=0.f,f1=0.f;
            if (!skip){
                const float* src=g_gif+(curr_p*Bb+b0)*G3;
                f0=src[tid];
                if (tid<272) f1=src[tid+NTHR];
            }
            mv_smem(sUg,h4f,ghp,tid,j,kh,k0c,kcC);
            if (!skip){
                gi_s[tid]=f0;
                if (tid<272) gi_s[tid+NTHR]=f1;
            }
            skip=false;
            __syncthreads();
            gates4(ghp,gi_s,G3,sgb1,h4f,(float*)0,tid);
            __syncthreads();
        } else {
            int next_p=curr_p+1;
            while (next_p<Tt && !obs_s[next_p]) next_p++;
            int step=1;
            while (curr_p+2*step<=next_p && step<=8) step<<=1;
            if (step>1) step>>=1;
            int lvl=(step==8)?3:((step==4)?2:((step==2)?1:0));
            int tf=curr_p+step;
            int fl=(step>1);

            // P1: hb = dict[curr+2*step]
            if (tid<400) hb4f[tid]=g_dict[((curr_p+2*step)*128+blk)*400+tid];
            __syncthreads();

            // P2: decoder partials over cat[h,hb]
            if (tid<800){
                int seg=tid/200, o=tid-seg*200;
                int r=o/50, jo=o-r*50;
                const float* dW=decW+lvl*10000+(seg*50)*50+jo;
                const float* hsrc=(seg<2)? (h4f+(seg&1)*200) : (hb4f+(seg&1)*200);
                float acc=0.f;
                #pragma unroll
                for (int kk=0;kk<50;kk++)
                    acc=fmaf(hsrc[kk*4+r], dW[kk*50], acc);
                decp[seg*200+o]=acc;
            }
            __syncthreads();

            // P3: reduce + relu -> dec4 interleaved [k*4+r]
            if (tid<200){
                int r=tid/50, jo=tid-r*50;
                int o=r*50+jo;
                float v=decp[o]+decp[200+o]+decp[400+o]+decp[600+o]+decB[lvl*50+jo];
                dec4[jo*4+r]=fmaxf(v,0.f);
            }
            __syncthreads();

            // P4: merged — fwd-gi || bwd-gi(if fl) || mean || hb(right+1) prefetch
            if (tid<300){
                u64 a01=dup2(g_bff[lvl*G3+tid]), a23=a01;
                const ulonglong2* dp=(const ulonglong2*)dec4;
                const float* Fp=g_Ff + (lvl*50)*G3 + tid;
                #pragma unroll
                for (int k=0;k<50;k++){
                    u64 w=dup2(Fp[k*G3]);
                    ulonglong2 x=dp[k];
                    a01=ffma2(x.x,w,a01); a23=ffma2(x.y,w,a23);
                }
                float f0,f1,f2,f3;
                asm("mov.b64 {%0,%1},%2;":"=f"(f0),"=f"(f1):"l"(a01));
                asm("mov.b64 {%0,%1},%2;":"=f"(f2),"=f"(f3):"l"(a23));
                if (fl){
                    float* dst=g_gif+(tf*Bb+b0)*G3+tid;
                    dst[0]=f0; dst[300]=f1; dst[600]=f2; dst[900]=f3;
                } else {
                    gi_s[tid]=f0; gi_s[300+tid]=f1; gi_s[600+tid]=f2; gi_s[900+tid]=f3;
                }
            } else if (tid<600){
                if (fl){
                    int jq=tid-300;
                    u64 a01=dup2(g_bfb[lvl*G3+jq]), a23=a01;
                    const ulonglong2* dp=(const ulonglong2*)dec4;
                    const float* Fp=g_Fb + (lvl*50)*G3 + jq;
                    #pragma unroll
                    for (int k=0;k<50;k++){
                        u64 w=dup2(Fp[k*G3]);
                        ulonglong2 x=dp[k];
                        a01=ffma2(x.x,w,a01); a23=ffma2(x.y,w,a23);
                    }
                    float f0,f1,f2,f3;
                    asm("mov.b64 {%0,%1},%2;":"=f"(f0),"=f"(f1):"l"(a01));
                    asm("mov.b64 {%0,%1},%2;":"=f"(f2),"=f"(f3):"l"(a23));
                    gi_s[jq]=f0; gi_s[300+jq]=f1; gi_s[600+jq]=f2; gi_s[900+jq]=f3;
                }
            } else if (tid<856){
                int idx=tid-600;
                int r=idx>>6, dcol=idx&63;
                const float* mW=meanW+lvl*3200;
                float acc=meanB[lvl*64+dcol];
                #pragma unroll
                for (int k=0;k<50;k++) acc=fmaf(dec4[k*4+r], mW[k*64+dcol], acc);
                g_states[(tf*Bb+b0+r)*65+dcol]=acc;
            } else {
                if (tid<860) g_states[(tf*Bb+b0+(tid-856))*65+64]=1.f;
                if (fl){
                    int e=tid-856;
                    float v[6];
                    #pragma unroll
                    for (int q=0;q<6;q++){ int i2=e+q*72; v[q]=(i2<400)? g_dict[((tf+1)*128+blk)*400+i2] : 0.f; }
                    #pragma unroll
                    for (int q=0;q<6;q++){ int i2=e+q*72; if (i2<400) hb4f[i2]=v[q]; }
                }
            }
            __syncthreads();

            if (fl){
                int right=tf, left=curr_p+step/2;
                mv_reg(uB,hb4f,ghp,tid,j,kh,k0c,kcC);
                __syncthreads();
                gates4(ghp,gi_s,G3,sbb1,hb4f,g_dict+(right*128+blk)*400,tid);
                __syncthreads();
                for (int ii=right-1; ii>=left; ii--){
                    mv_reg(uB,hb4f,ghp,tid,j,kh,k0c,kcC);
                    __syncthreads();
                    gates4(ghp,sb0,0,sbb1,hb4f,g_dict+(ii*128+blk)*400,tid);
                    __syncthreads();
                }
            } else {
                skip=true;
            }
            obs_s[tf]=1;
        }
    }
}

// tiled transpose: g_states[t][b][1+c] -> out[b][c][t]
__global__ void k_out(float* __restrict__ out){
    __shared__ float tile[64][65];
    int b=blockIdx.x, t0=blockIdx.y*64;
    int tid=threadIdx.x;
    for (int i=tid;i<4096;i+=256){
        int tt=i>>6, c=i&63;
        tile[tt][c]=g_states[((t0+tt)*Bb+b)*65+1+c];
    }
    __syncthreads();
    for (int i=tid;i<4096;i+=256){
        int c=i>>6, tt=i&63;
        out[(b*Dd+c)*Tt+t0+tt]=tile[tt][c];
    }
}

extern "C" void kernel_launch(void* const* d_in, const int* in_sizes, int n_in,
                              void* d_out, int out_size){
    const float* a    =(const float*)d_in[0];
    const float* gruW =(const float*)d_in[1];
    const float* gruU =(const float*)d_in[2];
    const float* gruB =(const float*)d_in[3];
    const float* bgruW=(const float*)d_in[4];
    const float* bgruU=(const float*)d_in[5];
    const float* bgruB=(const float*)d_in[6];
    const float* decW =(const float*)d_in[7];
    const float* decB =(const float*)d_in[8];
    const float* meanW=(const float*)d_in[9];
    const float* meanB=(const float*)d_in[10];
    float* out=(float*)d_out;

    cudaFuncSetAttribute(k_fwd, cudaFuncAttributeMaxDynamicSharedMemorySize, 37500*4);

    k_states<<<dim3(Bb,4),256>>>(a);
    dim3 g2(Tt*32,3);
    k_gi<<<g2,320>>>(gruW,gruB,bgruW,bgruB,meanW,meanB);
    k_back<<<Bb/RPB,NTHR>>>(bgruU,bgruB);
    k_fwd<<<Bb/RPB,NTHR,37500*4>>>(gruU,gruB,bgruU,bgruB,decW,decB,meanW,meanB);
    k_out<<<dim3(Bb,4),256>>>(out);
}